// round 7
// baseline (speedup 1.0000x reference)
#include <cuda_runtime.h>
#include <cuda_fp16.h>
#include <math.h>
#include <stdint.h>

#define BSZ 4096
#define DIM 256

// Tile-compacted scratch: dxx/dyy only upper triangle (528 tiles each),
// dxy all 1024 tiles. 2080 tiles x 128x128 fp16 = 68 MB.
#define TILES_SELF 528
#define TILES_T1   1056
#define TILES_ALL  2080
#define TILE_ELEMS 16384

__device__ __align__(16) __half g_dist[(size_t)TILES_ALL * TILE_ELEMS];
__device__ __align__(16) __half g_h16[2][BSZ * DIM];   // fp16 copies of xs/xt
__device__ float  g_norm[2][BSZ];
__device__ double g_distsum[3];
__device__ double g_expsum[3];

// ---------------------------------------------------------------------------
// Row squared-norms (fp32 inputs): one warp per row; block 0 also zeroes sums.
__global__ void norms_kernel(const float* __restrict__ xs,
                             const float* __restrict__ xt) {
    if (blockIdx.x == 0 && threadIdx.x < 3) {
        g_distsum[threadIdx.x] = 0.0;
        g_expsum[threadIdx.x] = 0.0;
    }
    int warp = threadIdx.x >> 5;
    int lane = threadIdx.x & 31;
    int row  = blockIdx.x * 8 + warp;        // 0..8191
    int which = (row >= BSZ) ? 1 : 0;
    int r = row - which * BSZ;
    const float* src = which ? xt : xs;
    const float4* p = (const float4*)(src + (size_t)r * DIM);
    float s = 0.f;
    #pragma unroll
    for (int i = lane; i < DIM / 4; i += 32) {
        float4 v = p[i];
        s += v.x * v.x + v.y * v.y + v.z * v.z + v.w * v.w;
    }
    #pragma unroll
    for (int o = 16; o > 0; o >>= 1) s += __shfl_xor_sync(0xffffffffu, s, o);
    if (lane == 0) g_norm[which][r] = s;
}

// ---------------------------------------------------------------------------
// fp32 -> fp16 pre-convert (4 MB out).
__global__ void convert_kernel(const float4* __restrict__ xs,
                               const float4* __restrict__ xt) {
    const int N4 = BSZ * DIM / 4;            // 262144 per tensor
    int i = blockIdx.x * blockDim.x + threadIdx.x;   // 0..524287
    int which = (i >= N4) ? 1 : 0;
    int j = i - which * N4;
    float4 v = (which ? xt : xs)[j];
    __half2 h0 = __floats2half2_rn(v.x, v.y);
    __half2 h1 = __floats2half2_rn(v.z, v.w);
    *(uint2*)&g_h16[which][(size_t)j * 4] = make_uint2(*(uint32_t*)&h0, *(uint32_t*)&h1);
}

// ---------------------------------------------------------------------------
// Tile decode: t -> (z, by, bx, weight). For z<2 only by<=bx tiles exist.
__device__ __forceinline__ void tri_decode(int i, int& by, int& bx) {
    int b = 0;
    while (i >= 32 - b) { i -= 32 - b; b++; }
    by = b; bx = b + i;
}
__device__ __forceinline__ void tile_decode(int t, int& z, int& by, int& bx,
                                            float& w) {
    if (t < TILES_SELF)      { z = 0; tri_decode(t, by, bx); }
    else if (t < TILES_T1)   { z = 1; tri_decode(t - TILES_SELF, by, bx); }
    else                     { z = 2; int l = t - TILES_T1; by = l >> 5; bx = l & 31; }
    w = (z < 2 && by != bx) ? 2.0f : 1.0f;
}

// ---------------------------------------------------------------------------
// fp16 HMMA distance GEMM: one 128x128 tile per CTA, 8 warps (2x4),
// warp tile 64x32. K=256 in 4 chunks of 64, cp.async double-buffered,
// m16n8k16 f16.f16.f32 mma. C-fragment layout identical to the tf32 k8 one.
// ---------------------------------------------------------------------------
#define CHUNK 64
#define SMH_STRIDE 72                      // halves per row (conflict-free)
#define SMH_TILE   (128 * SMH_STRIDE)      // 9216 halves = 18432 B per tile
#define SM_BYTES   (4 * SMH_TILE * 2)      // A0,A1,B0,B1 = 73728 bytes

__device__ __forceinline__ uint32_t smem_u32(const void* p) {
    uint32_t a;
    asm("{ .reg .u64 t; cvta.to.shared.u64 t, %1; cvt.u32.u64 %0, t; }" : "=r"(a) : "l"(p));
    return a;
}
__device__ __forceinline__ void mma_f16(float* c, const uint32_t* a, const uint32_t* b) {
    asm volatile(
        "mma.sync.aligned.m16n8k16.row.col.f32.f16.f16.f32 "
        "{%0,%1,%2,%3}, {%4,%5,%6,%7}, {%8,%9}, {%0,%1,%2,%3};"
        : "+f"(c[0]), "+f"(c[1]), "+f"(c[2]), "+f"(c[3])
        : "r"(a[0]), "r"(a[1]), "r"(a[2]), "r"(a[3]), "r"(b[0]), "r"(b[1]));
}

__global__ void __launch_bounds__(256, 2)
dist_tc_kernel() {
    extern __shared__ __half smh[];
    __shared__ double red[256];

    int z, by, bx; float w;
    tile_decode(blockIdx.x, z, by, bx, w);

    const __half* Am = g_h16[(z == 1) ? 1 : 0];
    const __half* Bm = g_h16[(z == 0) ? 0 : 1];
    const int za = (z == 1) ? 1 : 0;
    const int zb = (z == 0) ? 0 : 1;
    const int rowBase = by * 128;
    const int colBase = bx * 128;

    const int tid = threadIdx.x;
    const int wid = tid >> 5;
    const int lid = tid & 31;
    const int wm = wid >> 2;
    const int wn = wid & 3;
    const int l4 = lid >> 2;       // groupID 0..7
    const int lk = lid & 3;        // threadID in group
    const int mrow0 = wm * 64;
    const int ncol0 = wn * 32;

    float acc[4][4][4];
    #pragma unroll
    for (int i = 0; i < 4; i++)
        #pragma unroll
        for (int j = 0; j < 4; j++)
            #pragma unroll
            for (int u = 0; u < 4; u++) acc[i][j][u] = 0.f;

    const uint32_t smb = smem_u32(smh);

    // One chunk = 128 rows x 64 halves for A and B. 2048 x 16B cp.asyncs.
    auto load_chunk = [&](int c, int buf) {
        const int k0 = c * CHUNK;
        #pragma unroll
        for (int it = 0; it < 8; it++) {
            int idx = it * 256 + tid;          // 0..2047
            int mat = idx >> 10;               // 0=A, 1=B
            int rem = idx & 1023;
            int row = rem >> 3;                // 0..127
            int g   = rem & 7;                 // 8-half group
            const __half* gp = (mat ? Bm : Am) +
                (size_t)((mat ? colBase : rowBase) + row) * DIM + k0 + g * 8;
            uint32_t sa = smb + ((mat * 2 + buf) * SMH_TILE + row * SMH_STRIDE + g * 8) * 2;
            asm volatile("cp.async.cg.shared.global [%0], [%1], 16;"
                         :: "r"(sa), "l"(gp));
        }
        asm volatile("cp.async.commit_group;");
    };

    load_chunk(0, 0);

    #pragma unroll
    for (int c = 0; c < 4; c++) {
        const int buf = c & 1;
        if (c < 3) {
            load_chunk(c + 1, buf ^ 1);
            asm volatile("cp.async.wait_group 1;");
        } else {
            asm volatile("cp.async.wait_group 0;");
        }
        __syncthreads();

        const __half* A = smh + buf * SMH_TILE;
        const __half* B = smh + (2 + buf) * SMH_TILE;

        #pragma unroll
        for (int ks = 0; ks < 4; ks++) {
            const int kb = ks * 16;
            uint32_t a[4][4], b[4][2];
            #pragma unroll
            for (int mt = 0; mt < 4; mt++) {
                int r = mrow0 + mt * 16 + l4;
                a[mt][0] = *(const uint32_t*)&A[r * SMH_STRIDE + kb + 2 * lk];
                a[mt][1] = *(const uint32_t*)&A[(r + 8) * SMH_STRIDE + kb + 2 * lk];
                a[mt][2] = *(const uint32_t*)&A[r * SMH_STRIDE + kb + 8 + 2 * lk];
                a[mt][3] = *(const uint32_t*)&A[(r + 8) * SMH_STRIDE + kb + 8 + 2 * lk];
            }
            #pragma unroll
            for (int nt = 0; nt < 4; nt++) {
                int n = ncol0 + nt * 8 + l4;
                b[nt][0] = *(const uint32_t*)&B[n * SMH_STRIDE + kb + 2 * lk];
                b[nt][1] = *(const uint32_t*)&B[n * SMH_STRIDE + kb + 8 + 2 * lk];
            }
            #pragma unroll
            for (int mt = 0; mt < 4; mt++)
                #pragma unroll
                for (int nt = 0; nt < 4; nt++)
                    mma_f16(acc[mt][nt], a[mt], b[nt]);
        }
        __syncthreads();
    }

    // Epilogue: d = sqrt(max(na + nb - 2*dot, 0)); exact self-diagonal -> 0.
    float na0[4], na1[4], nb0[4], nb1[4];
    #pragma unroll
    for (int mt = 0; mt < 4; mt++) {
        int r = rowBase + mrow0 + mt * 16 + l4;
        na0[mt] = g_norm[za][r];
        na1[mt] = g_norm[za][r + 8];
    }
    #pragma unroll
    for (int nt = 0; nt < 4; nt++) {
        int cc = colBase + ncol0 + nt * 8 + 2 * lk;
        nb0[nt] = g_norm[zb][cc];
        nb1[nt] = g_norm[zb][cc + 1];
    }

    const bool selfdiag = (z < 2) && (by == bx);
    __half* gd = g_dist + (size_t)blockIdx.x * TILE_ELEMS;
    float lsum = 0.f;
    #pragma unroll
    for (int mt = 0; mt < 4; mt++) {
        int lr0 = mrow0 + mt * 16 + l4;
        #pragma unroll
        for (int nt = 0; nt < 4; nt++) {
            int lc = ncol0 + nt * 8 + 2 * lk;
            float* ac = acc[mt][nt];
            float d00 = sqrtf(fmaxf(na0[mt] + nb0[nt] - 2.f * ac[0], 0.f));
            float d01 = sqrtf(fmaxf(na0[mt] + nb1[nt] - 2.f * ac[1], 0.f));
            float d10 = sqrtf(fmaxf(na1[mt] + nb0[nt] - 2.f * ac[2], 0.f));
            float d11 = sqrtf(fmaxf(na1[mt] + nb1[nt] - 2.f * ac[3], 0.f));
            if (selfdiag) {
                if (lr0 == lc)         d00 = 0.f;
                if (lr0 == lc + 1)     d01 = 0.f;
                if (lr0 + 8 == lc)     d10 = 0.f;
                if (lr0 + 8 == lc + 1) d11 = 0.f;
            }
            lsum += (d00 + d01) + (d10 + d11);
            *(__half2*)(gd + lr0 * 128 + lc)       = __floats2half2_rn(d00, d01);
            *(__half2*)(gd + (lr0 + 8) * 128 + lc) = __floats2half2_rn(d10, d11);
        }
    }

    red[tid] = (double)lsum;
    __syncthreads();
    #pragma unroll
    for (int s = 128; s > 0; s >>= 1) {
        if (tid < s) red[tid] += red[tid + s];
        __syncthreads();
    }
    if (tid == 0) atomicAdd(&g_distsum[z], red[0] * (double)w);
}

// ---------------------------------------------------------------------------
// Exponent pass, one CTA per tile. alphas are powers of two: with
// e = exp(-d/(4m)) the five kernels are e, e^2, e^4, e^8, e^16.
__global__ void exp_kernel() {
    __shared__ double red[256];
    int z, by, bx; float w;
    tile_decode(blockIdx.x, z, by, bx, w);

    double m = g_distsum[z] * (1.0 / ((double)BSZ * (double)BSZ));
    float c = (float)(-1.4426950408889634 / (4.0 * m));

    const uint4* src = (const uint4*)(g_dist + (size_t)blockIdx.x * TILE_ELEMS);
    float lsum = 0.f;
    #pragma unroll
    for (int it = 0; it < 8; it++) {
        uint4 v = src[it * 256 + threadIdx.x];
        uint32_t ww[4] = {v.x, v.y, v.z, v.w};
        #pragma unroll
        for (int u = 0; u < 4; u++) {
            float2 f = __half22float2(*(__half2*)&ww[u]);
            float d2[2] = {f.x, f.y};
            #pragma unroll
            for (int q = 0; q < 2; q++) {
                float t = d2[q] * c;
                float e;
                asm("ex2.approx.ftz.f32 %0, %1;" : "=f"(e) : "f"(t));
                float e2 = e * e, e4 = e2 * e2, e8 = e4 * e4, e16 = e8 * e8;
                lsum += (e + e2) + (e4 + e8) + e16;
            }
        }
    }

    red[threadIdx.x] = (double)lsum;
    __syncthreads();
    #pragma unroll
    for (int s = 128; s > 0; s >>= 1) {
        if (threadIdx.x < s) red[threadIdx.x] += red[threadIdx.x + s];
        __syncthreads();
    }
    if (threadIdx.x == 0) atomicAdd(&g_expsum[z], red[0] * (double)w);
}

// ---------------------------------------------------------------------------
__global__ void final_kernel(float* out) {
    double total = g_expsum[0] + g_expsum[1] - 2.0 * g_expsum[2];
    double v = total / ((double)BSZ * ((double)BSZ - 1.0));
    float loss = sqrtf((float)v);
    out[0] = isnan(loss) ? 0.f : loss;
}

// ---------------------------------------------------------------------------
extern "C" void kernel_launch(void* const* d_in, const int* in_sizes, int n_in,
                              void* d_out, int out_size) {
    const float* xs = (const float*)d_in[0];
    const float* xt = (const float*)d_in[1];
    float* out = (float*)d_out;

    static int configured = 0;
    if (!configured) {
        cudaFuncSetAttribute(dist_tc_kernel,
                             cudaFuncAttributeMaxDynamicSharedMemorySize, SM_BYTES);
        configured = 1;
    }

    norms_kernel<<<1024, 256>>>(xs, xt);
    convert_kernel<<<2048, 256>>>((const float4*)xs, (const float4*)xt);
    dist_tc_kernel<<<TILES_ALL, 256, SM_BYTES>>>();
    exp_kernel<<<TILES_ALL, 256>>>();
    final_kernel<<<1, 1>>>(out);
}

// round 13
// speedup vs baseline: 1.0202x; 1.0202x over previous
#include <cuda_runtime.h>
#include <cuda_fp16.h>
#include <math.h>
#include <stdint.h>

#define BSZ 4096
#define DIM 256

// Tile-compacted scratch: dxx/dyy only upper triangle (528 tiles each),
// dxy all 1024 tiles. 2080 tiles x 128x128 fp16 = 68 MB.
#define TILES_SELF 528
#define TILES_T1   1056
#define TILES_ALL  2080
#define TILE_ELEMS 16384

__device__ __align__(16) __half g_dist[(size_t)TILES_ALL * TILE_ELEMS];
__device__ float  g_norm[2][BSZ];
__device__ double g_distsum[3];
__device__ double g_expsum[3];

// ---------------------------------------------------------------------------
// Row squared-norms: one warp per row (8192 rows); block 0 zeroes accumulators.
__global__ void norms_kernel(const float* __restrict__ xs,
                             const float* __restrict__ xt) {
    if (blockIdx.x == 0 && threadIdx.x < 3) {
        g_distsum[threadIdx.x] = 0.0;
        g_expsum[threadIdx.x] = 0.0;
    }
    int warp = threadIdx.x >> 5;
    int lane = threadIdx.x & 31;
    int row  = blockIdx.x * 8 + warp;        // 0..8191
    int which = (row >= BSZ) ? 1 : 0;
    int r = row - which * BSZ;
    const float* src = which ? xt : xs;
    const float4* p = (const float4*)(src + (size_t)r * DIM);
    float s = 0.f;
    #pragma unroll
    for (int i = lane; i < DIM / 4; i += 32) {
        float4 v = p[i];
        s += v.x * v.x + v.y * v.y + v.z * v.z + v.w * v.w;
    }
    #pragma unroll
    for (int o = 16; o > 0; o >>= 1) s += __shfl_xor_sync(0xffffffffu, s, o);
    if (lane == 0) g_norm[which][r] = s;
}

// ---------------------------------------------------------------------------
// Tile decode: t -> (z, by, bx, weight). For z<2 only by<=bx tiles exist.
__device__ __forceinline__ void tri_decode(int i, int& by, int& bx) {
    int b = 0;
    while (i >= 32 - b) { i -= 32 - b; b++; }
    by = b; bx = b + i;
}
__device__ __forceinline__ void tile_decode(int t, int& z, int& by, int& bx,
                                            float& w) {
    if (t < TILES_SELF)      { z = 0; tri_decode(t, by, bx); }
    else if (t < TILES_T1)   { z = 1; tri_decode(t - TILES_SELF, by, bx); }
    else                     { z = 2; int l = t - TILES_T1; by = l >> 5; bx = l & 31; }
    w = (z < 2 && by != bx) ? 2.0f : 1.0f;
}

// ---------------------------------------------------------------------------
// tf32 HMMA distance GEMM: one 128x128 tile per CTA, 8 warps (2x4).
// K=256 in 8 chunks of 32, cp.async double-buffered, m16n8k8 tf32 mma.
// (Proven config from R5: rel_err 2.7e-4, MMA-rate bound.)
// ---------------------------------------------------------------------------
#define CHUNK 32
#define SM_STRIDE 36
#define SM_TILE   (128 * SM_STRIDE)
#define SM_BYTES  (4 * SM_TILE * 4)        // 73728 bytes

__device__ __forceinline__ uint32_t smem_u32(const void* p) {
    uint32_t a;
    asm("{ .reg .u64 t; cvta.to.shared.u64 t, %1; cvt.u32.u64 %0, t; }" : "=r"(a) : "l"(p));
    return a;
}
__device__ __forceinline__ uint32_t to_tf32(float f) {
    uint32_t u;
    asm("cvt.rna.tf32.f32 %0, %1;" : "=r"(u) : "f"(f));
    return u;
}
__device__ __forceinline__ void mma_tf32(float* c, const uint32_t* a, const uint32_t* b) {
    asm volatile(
        "mma.sync.aligned.m16n8k8.row.col.f32.tf32.tf32.f32 "
        "{%0,%1,%2,%3}, {%4,%5,%6,%7}, {%8,%9}, {%0,%1,%2,%3};"
        : "+f"(c[0]), "+f"(c[1]), "+f"(c[2]), "+f"(c[3])
        : "r"(a[0]), "r"(a[1]), "r"(a[2]), "r"(a[3]), "r"(b[0]), "r"(b[1]));
}

__global__ void __launch_bounds__(256, 2)
dist_tc_kernel(const float* __restrict__ xs, const float* __restrict__ xt) {
    extern __shared__ float sm[];
    __shared__ double red[256];

    int z, by, bx; float w;
    tile_decode(blockIdx.x, z, by, bx, w);

    const float* Am = (z == 1) ? xt : xs;
    const float* Bm = (z == 0) ? xs : xt;
    const int za = (z == 1) ? 1 : 0;
    const int zb = (z == 0) ? 0 : 1;
    const int rowBase = by * 128;
    const int colBase = bx * 128;

    const int tid = threadIdx.x;
    const int wid = tid >> 5;
    const int lid = tid & 31;
    const int wm = wid >> 2;
    const int wn = wid & 3;
    const int l4 = lid >> 2;
    const int lk = lid & 3;
    const int mrow0 = wm * 64;
    const int ncol0 = wn * 32;

    float acc[4][4][4];
    #pragma unroll
    for (int i = 0; i < 4; i++)
        #pragma unroll
        for (int j = 0; j < 4; j++)
            #pragma unroll
            for (int u = 0; u < 4; u++) acc[i][j][u] = 0.f;

    const uint32_t smb = smem_u32(sm);

    auto load_chunk = [&](int c, int buf) {
        const int k0 = c * CHUNK;
        #pragma unroll
        for (int it = 0; it < 8; it++) {
            int idx = it * 256 + tid;
            int mat = idx >> 10;
            int rem = idx & 1023;
            int row = rem >> 3;
            int g   = rem & 7;
            const float* gp = (mat ? Bm : Am) +
                (size_t)((mat ? colBase : rowBase) + row) * DIM + k0 + g * 4;
            uint32_t sa = smb + ((mat * 2 + buf) * SM_TILE + row * SM_STRIDE + g * 4) * 4;
            asm volatile("cp.async.cg.shared.global [%0], [%1], 16;"
                         :: "r"(sa), "l"(gp));
        }
        asm volatile("cp.async.commit_group;");
    };

    load_chunk(0, 0);

    for (int c = 0; c < 8; c++) {
        const int buf = c & 1;
        if (c < 7) {
            load_chunk(c + 1, buf ^ 1);
            asm volatile("cp.async.wait_group 1;");
        } else {
            asm volatile("cp.async.wait_group 0;");
        }
        __syncthreads();

        const float* A = sm + buf * SM_TILE;
        const float* B = sm + (2 + buf) * SM_TILE;

        #pragma unroll
        for (int ks = 0; ks < 4; ks++) {
            const int kb = ks * 8;
            uint32_t a[4][4], b[4][2];
            #pragma unroll
            for (int mt = 0; mt < 4; mt++) {
                int r = mrow0 + mt * 16 + l4;
                a[mt][0] = to_tf32(A[r * SM_STRIDE + kb + lk]);
                a[mt][1] = to_tf32(A[(r + 8) * SM_STRIDE + kb + lk]);
                a[mt][2] = to_tf32(A[r * SM_STRIDE + kb + lk + 4]);
                a[mt][3] = to_tf32(A[(r + 8) * SM_STRIDE + kb + lk + 4]);
            }
            #pragma unroll
            for (int nt = 0; nt < 4; nt++) {
                int cc = ncol0 + nt * 8 + l4;
                b[nt][0] = to_tf32(B[cc * SM_STRIDE + kb + lk]);
                b[nt][1] = to_tf32(B[cc * SM_STRIDE + kb + lk + 4]);
            }
            #pragma unroll
            for (int mt = 0; mt < 4; mt++)
                #pragma unroll
                for (int nt = 0; nt < 4; nt++)
                    mma_tf32(acc[mt][nt], a[mt], b[nt]);
        }
        __syncthreads();
    }

    // Epilogue: d = sqrt(max(na + nb - 2*dot, 0)); exact self-diagonal -> 0.
    float na0[4], na1[4], nb0[4], nb1[4];
    #pragma unroll
    for (int mt = 0; mt < 4; mt++) {
        int r = rowBase + mrow0 + mt * 16 + l4;
        na0[mt] = g_norm[za][r];
        na1[mt] = g_norm[za][r + 8];
    }
    #pragma unroll
    for (int nt = 0; nt < 4; nt++) {
        int cc = colBase + ncol0 + nt * 8 + 2 * lk;
        nb0[nt] = g_norm[zb][cc];
        nb1[nt] = g_norm[zb][cc + 1];
    }

    const bool selfdiag = (z < 2) && (by == bx);
    __half* gd = g_dist + (size_t)blockIdx.x * TILE_ELEMS;
    float lsum = 0.f;
    #pragma unroll
    for (int mt = 0; mt < 4; mt++) {
        int lr0 = mrow0 + mt * 16 + l4;
        #pragma unroll
        for (int nt = 0; nt < 4; nt++) {
            int lc = ncol0 + nt * 8 + 2 * lk;
            float* ac = acc[mt][nt];
            float d00 = sqrtf(fmaxf(na0[mt] + nb0[nt] - 2.f * ac[0], 0.f));
            float d01 = sqrtf(fmaxf(na0[mt] + nb1[nt] - 2.f * ac[1], 0.f));
            float d10 = sqrtf(fmaxf(na1[mt] + nb0[nt] - 2.f * ac[2], 0.f));
            float d11 = sqrtf(fmaxf(na1[mt] + nb1[nt] - 2.f * ac[3], 0.f));
            if (selfdiag) {
                if (lr0 == lc)         d00 = 0.f;
                if (lr0 == lc + 1)     d01 = 0.f;
                if (lr0 + 8 == lc)     d10 = 0.f;
                if (lr0 + 8 == lc + 1) d11 = 0.f;
            }
            lsum += (d00 + d01) + (d10 + d11);
            *(__half2*)(gd + lr0 * 128 + lc)       = __floats2half2_rn(d00, d01);
            *(__half2*)(gd + (lr0 + 8) * 128 + lc) = __floats2half2_rn(d10, d11);
        }
    }

    red[tid] = (double)lsum;
    __syncthreads();
    #pragma unroll
    for (int s = 128; s > 0; s >>= 1) {
        if (tid < s) red[tid] += red[tid + s];
        __syncthreads();
    }
    if (tid == 0) atomicAdd(&g_distsum[z], red[0] * (double)w);
}

// ---------------------------------------------------------------------------
// Exponent pass, one CTA per tile. e = exp(-d/(4m)) via f32 MUFU ex2;
// power chain e,e^2,e^4,e^8,e^16 and partial sums in PACKED f32x2
// (mul.rn.f32x2 / add.rn.f32x2 -- exact IEEE fp32 RN, numerically identical
// to the scalar fp32 version that passed at 2.7e-4; halves issue slots).
typedef unsigned long long ull_t;
__device__ __forceinline__ ull_t f2_pack(float lo, float hi) {
    ull_t r;
    asm("mov.b64 %0, {%1, %2};" : "=l"(r) : "f"(lo), "f"(hi));
    return r;
}
__device__ __forceinline__ ull_t f2_mul(ull_t a, ull_t b) {
    ull_t r;
    asm("mul.rn.f32x2 %0, %1, %2;" : "=l"(r) : "l"(a), "l"(b));
    return r;
}
__device__ __forceinline__ ull_t f2_add(ull_t a, ull_t b) {
    ull_t r;
    asm("add.rn.f32x2 %0, %1, %2;" : "=l"(r) : "l"(a), "l"(b));
    return r;
}

__global__ void __launch_bounds__(256)
exp_kernel() {
    __shared__ double red[256];
    int z, by, bx; float w;
    tile_decode(blockIdx.x, z, by, bx, w);

    double m = g_distsum[z] * (1.0 / ((double)BSZ * (double)BSZ));
    float c = (float)(-1.4426950408889634 / (4.0 * m));

    const uint4* src = (const uint4*)(g_dist + (size_t)blockIdx.x * TILE_ELEMS);

    // Batch all 8 loads first (MLP=8), then process.
    uint4 v[8];
    #pragma unroll
    for (int it = 0; it < 8; it++) v[it] = src[it * 256 + threadIdx.x];

    ull_t s2 = 0ull;                        // packed (0.f, 0.f)
    #pragma unroll
    for (int it = 0; it < 8; it++) {
        uint32_t ww[4] = {v[it].x, v[it].y, v[it].z, v[it].w};
        #pragma unroll
        for (int u = 0; u < 4; u++) {
            float2 f = __half22float2(*(__half2*)&ww[u]);
            float e0, e1;
            asm("ex2.approx.ftz.f32 %0, %1;" : "=f"(e0) : "f"(f.x * c));
            asm("ex2.approx.ftz.f32 %0, %1;" : "=f"(e1) : "f"(f.y * c));
            ull_t e  = f2_pack(e0, e1);
            ull_t q2 = f2_mul(e, e);
            ull_t q4 = f2_mul(q2, q2);
            ull_t q8 = f2_mul(q4, q4);
            ull_t q16 = f2_mul(q8, q8);
            s2 = f2_add(s2, f2_add(f2_add(e, q2), f2_add(q4, q8)));
            s2 = f2_add(s2, q16);
        }
    }
    float sl, sh;
    asm("mov.b64 {%0, %1}, %2;" : "=f"(sl), "=f"(sh) : "l"(s2));
    float lsum = sl + sh;

    red[threadIdx.x] = (double)lsum;
    __syncthreads();
    #pragma unroll
    for (int s = 128; s > 0; s >>= 1) {
        if (threadIdx.x < s) red[threadIdx.x] += red[threadIdx.x + s];
        __syncthreads();
    }
    if (threadIdx.x == 0) atomicAdd(&g_expsum[z], red[0] * (double)w);
}

// ---------------------------------------------------------------------------
__global__ void final_kernel(float* out) {
    double total = g_expsum[0] + g_expsum[1] - 2.0 * g_expsum[2];
    double v = total / ((double)BSZ * ((double)BSZ - 1.0));
    float loss = sqrtf((float)v);
    out[0] = isnan(loss) ? 0.f : loss;
}

// ---------------------------------------------------------------------------
extern "C" void kernel_launch(void* const* d_in, const int* in_sizes, int n_in,
                              void* d_out, int out_size) {
    const float* xs = (const float*)d_in[0];
    const float* xt = (const float*)d_in[1];
    float* out = (float*)d_out;

    static int configured = 0;
    if (!configured) {
        cudaFuncSetAttribute(dist_tc_kernel,
                             cudaFuncAttributeMaxDynamicSharedMemorySize, SM_BYTES);
        configured = 1;
    }

    norms_kernel<<<1024, 256>>>(xs, xt);
    dist_tc_kernel<<<TILES_ALL, 256, SM_BYTES>>>(xs, xt);
    exp_kernel<<<TILES_ALL, 256>>>();
    final_kernel<<<1, 1>>>(out);
}

// round 14
// speedup vs baseline: 1.0872x; 1.0657x over previous
#include <cuda_runtime.h>
#include <cuda_fp16.h>
#include <math.h>
#include <stdint.h>

#define BSZ 4096
#define DIM 256
#define QSCALE 25.0f
#define QINV   0.04f

// Tile-compacted scratch: dxx/dyy upper triangle (528 tiles each), dxy all
// 1024. 2080 tiles x 128x128 fp16 = 68 MB. Plus int8 inputs (2 MB).
#define TILES_SELF 528
#define TILES_T1   1056
#define TILES_ALL  2080
#define TILE_ELEMS 16384

__device__ __align__(16) __half g_dist[(size_t)TILES_ALL * TILE_ELEMS];
__device__ __align__(16) char   g_q[2][BSZ * DIM];    // int8 quantized inputs
__device__ int    g_normi[2][BSZ];                    // |q|^2 (integer, exact)
__device__ double g_distsum[3];
__device__ double g_expsum[3];

// ---------------------------------------------------------------------------
// Prep: quantize to s8 (q = round(25x), clamp +-127), integer row norms,
// zero accumulators. One warp per row.
__global__ void prep_kernel(const float* __restrict__ xs,
                            const float* __restrict__ xt) {
    if (blockIdx.x == 0 && threadIdx.x < 3) {
        g_distsum[threadIdx.x] = 0.0;
        g_expsum[threadIdx.x] = 0.0;
    }
    int warp = threadIdx.x >> 5;
    int lane = threadIdx.x & 31;
    int row  = blockIdx.x * 8 + warp;        // 0..8191
    int which = (row >= BSZ) ? 1 : 0;
    int r = row - which * BSZ;
    const float* src = (which ? xt : xs) + (size_t)r * DIM;

    float4 v0 = *(const float4*)(src + lane * 8);
    float4 v1 = *(const float4*)(src + lane * 8 + 4);
    float f[8] = {v0.x, v0.y, v0.z, v0.w, v1.x, v1.y, v1.z, v1.w};
    int q[8], nsum = 0;
    #pragma unroll
    for (int u = 0; u < 8; u++) {
        q[u] = __float2int_rn(fminf(fmaxf(f[u] * QSCALE, -127.f), 127.f));
        nsum += q[u] * q[u];
    }
    uint32_t lo = (q[0] & 255) | ((q[1] & 255) << 8) |
                  ((q[2] & 255) << 16) | ((uint32_t)(q[3] & 255) << 24);
    uint32_t hi = (q[4] & 255) | ((q[5] & 255) << 8) |
                  ((q[6] & 255) << 16) | ((uint32_t)(q[7] & 255) << 24);
    *(uint2*)(g_q[which] + (size_t)r * DIM + lane * 8) = make_uint2(lo, hi);

    #pragma unroll
    for (int o = 16; o > 0; o >>= 1) nsum += __shfl_xor_sync(0xffffffffu, nsum, o);
    if (lane == 0) g_normi[which][r] = nsum;
}

// ---------------------------------------------------------------------------
// Tile decode: t -> (z, by, bx, weight). For z<2 only by<=bx tiles exist.
__device__ __forceinline__ void tri_decode(int i, int& by, int& bx) {
    int b = 0;
    while (i >= 32 - b) { i -= 32 - b; b++; }
    by = b; bx = b + i;
}
__device__ __forceinline__ void tile_decode(int t, int& z, int& by, int& bx,
                                            float& w) {
    if (t < TILES_SELF)      { z = 0; tri_decode(t, by, bx); }
    else if (t < TILES_T1)   { z = 1; tri_decode(t - TILES_SELF, by, bx); }
    else                     { z = 2; int l = t - TILES_T1; by = l >> 5; bx = l & 31; }
    w = (z < 2 && by != bx) ? 2.0f : 1.0f;
}

// ---------------------------------------------------------------------------
// int8 IMMA distance GEMM: one 128x128 tile per CTA, 8 warps (2x4),
// warp tile 64x32. K=256 in 2 chunks of 128 bytes, cp.async double-buffered,
// m16n8k32 s8.s8.s32. 625*d^2 is an exact integer => diagonal exactly 0.
// ---------------------------------------------------------------------------
#define SMB_STRIDE 144                     // bytes per row (conflict-free)
#define SMB_TILE   (128 * SMB_STRIDE)      // 18432 B per tile buffer
#define SM_BYTES   (4 * SMB_TILE)          // A0,A1,B0,B1 = 73728 bytes

__device__ __forceinline__ uint32_t smem_u32(const void* p) {
    uint32_t a;
    asm("{ .reg .u64 t; cvta.to.shared.u64 t, %1; cvt.u32.u64 %0, t; }" : "=r"(a) : "l"(p));
    return a;
}
__device__ __forceinline__ void mma_s8(int* c, const uint32_t* a, const uint32_t* b) {
    asm volatile(
        "mma.sync.aligned.m16n8k32.row.col.s32.s8.s8.s32 "
        "{%0,%1,%2,%3}, {%4,%5,%6,%7}, {%8,%9}, {%0,%1,%2,%3};"
        : "+r"(c[0]), "+r"(c[1]), "+r"(c[2]), "+r"(c[3])
        : "r"(a[0]), "r"(a[1]), "r"(a[2]), "r"(a[3]), "r"(b[0]), "r"(b[1]));
}

__global__ void __launch_bounds__(256, 2)
dist_tc_kernel() {
    extern __shared__ char smc[];
    __shared__ double red[256];

    int z, by, bx; float w;
    tile_decode(blockIdx.x, z, by, bx, w);

    const char* Am = g_q[(z == 1) ? 1 : 0];
    const char* Bm = g_q[(z == 0) ? 0 : 1];
    const int za = (z == 1) ? 1 : 0;
    const int zb = (z == 0) ? 0 : 1;
    const int rowBase = by * 128;
    const int colBase = bx * 128;

    const int tid = threadIdx.x;
    const int wid = tid >> 5;
    const int lid = tid & 31;
    const int wm = wid >> 2;
    const int wn = wid & 3;
    const int l4 = lid >> 2;       // groupID 0..7
    const int lk = lid & 3;        // threadID in group
    const int mrow0 = wm * 64;
    const int ncol0 = wn * 32;

    int acc[4][4][4];
    #pragma unroll
    for (int i = 0; i < 4; i++)
        #pragma unroll
        for (int j = 0; j < 4; j++)
            #pragma unroll
            for (int u = 0; u < 4; u++) acc[i][j][u] = 0;

    const uint32_t smb = smem_u32(smc);

    // One chunk = 128 rows x 128 bytes for A and B: 2048 x 16B cp.asyncs.
    auto load_chunk = [&](int c, int buf) {
        const int k0 = c * 128;
        #pragma unroll
        for (int it = 0; it < 8; it++) {
            int idx = it * 256 + tid;          // 0..2047
            int mat = idx >> 10;               // 0=A, 1=B
            int rem = idx & 1023;
            int row = rem >> 3;                // 0..127
            int g   = rem & 7;                 // 16B group
            const char* gp = (mat ? Bm : Am) +
                (size_t)((mat ? colBase : rowBase) + row) * DIM + k0 + g * 16;
            uint32_t sa = smb + (mat * 2 + buf) * SMB_TILE + row * SMB_STRIDE + g * 16;
            asm volatile("cp.async.cg.shared.global [%0], [%1], 16;"
                         :: "r"(sa), "l"(gp));
        }
        asm volatile("cp.async.commit_group;");
    };

    load_chunk(0, 0);

    #pragma unroll
    for (int c = 0; c < 2; c++) {
        const int buf = c;
        if (c < 1) {
            load_chunk(1, 1);
            asm volatile("cp.async.wait_group 1;");
        } else {
            asm volatile("cp.async.wait_group 0;");
        }
        __syncthreads();

        const char* A = smc + buf * SMB_TILE;
        const char* B = smc + (2 + buf) * SMB_TILE;

        #pragma unroll
        for (int ks = 0; ks < 4; ks++) {
            const int kb = ks * 32;
            uint32_t a[4][4], b[4][2];
            #pragma unroll
            for (int mt = 0; mt < 4; mt++) {
                int r = mrow0 + mt * 16 + l4;
                a[mt][0] = *(const uint32_t*)&A[r * SMB_STRIDE + kb + 4 * lk];
                a[mt][1] = *(const uint32_t*)&A[(r + 8) * SMB_STRIDE + kb + 4 * lk];
                a[mt][2] = *(const uint32_t*)&A[r * SMB_STRIDE + kb + 16 + 4 * lk];
                a[mt][3] = *(const uint32_t*)&A[(r + 8) * SMB_STRIDE + kb + 16 + 4 * lk];
            }
            #pragma unroll
            for (int nt = 0; nt < 4; nt++) {
                int n = ncol0 + nt * 8 + l4;
                b[nt][0] = *(const uint32_t*)&B[n * SMB_STRIDE + kb + 4 * lk];
                b[nt][1] = *(const uint32_t*)&B[n * SMB_STRIDE + kb + 16 + 4 * lk];
            }
            #pragma unroll
            for (int mt = 0; mt < 4; mt++)
                #pragma unroll
                for (int nt = 0; nt < 4; nt++)
                    mma_s8(acc[mt][nt], a[mt], b[nt]);
        }
        __syncthreads();
    }

    // Epilogue: 625*d^2 = na + nb - 2*dot (exact int), d = sqrt(.)/25.
    int na0[4], na1[4], nb0[4], nb1[4];
    #pragma unroll
    for (int mt = 0; mt < 4; mt++) {
        int r = rowBase + mrow0 + mt * 16 + l4;
        na0[mt] = g_normi[za][r];
        na1[mt] = g_normi[za][r + 8];
    }
    #pragma unroll
    for (int nt = 0; nt < 4; nt++) {
        int cc = colBase + ncol0 + nt * 8 + 2 * lk;
        nb0[nt] = g_normi[zb][cc];
        nb1[nt] = g_normi[zb][cc + 1];
    }

    __half* gd = g_dist + (size_t)blockIdx.x * TILE_ELEMS;
    float lsum = 0.f;
    #pragma unroll
    for (int mt = 0; mt < 4; mt++) {
        int lr0 = mrow0 + mt * 16 + l4;
        #pragma unroll
        for (int nt = 0; nt < 4; nt++) {
            int lc = ncol0 + nt * 8 + 2 * lk;
            int* ac = acc[mt][nt];
            float d00 = sqrtf((float)(na0[mt] + nb0[nt] - 2 * ac[0])) * QINV;
            float d01 = sqrtf((float)(na0[mt] + nb1[nt] - 2 * ac[1])) * QINV;
            float d10 = sqrtf((float)(na1[mt] + nb0[nt] - 2 * ac[2])) * QINV;
            float d11 = sqrtf((float)(na1[mt] + nb1[nt] - 2 * ac[3])) * QINV;
            lsum += (d00 + d01) + (d10 + d11);
            *(__half2*)(gd + lr0 * 128 + lc)       = __floats2half2_rn(d00, d01);
            *(__half2*)(gd + (lr0 + 8) * 128 + lc) = __floats2half2_rn(d10, d11);
        }
    }

    red[tid] = (double)lsum;
    __syncthreads();
    #pragma unroll
    for (int s = 128; s > 0; s >>= 1) {
        if (tid < s) red[tid] += red[tid + s];
        __syncthreads();
    }
    if (tid == 0) atomicAdd(&g_distsum[z], red[0] * (double)w);
}

// ---------------------------------------------------------------------------
// Exponent pass (PROVEN R9 config): f32 MUFU ex2; power chain + sums in
// packed f32x2 (exact IEEE fp32 RN). One CTA per tile.
typedef unsigned long long ull_t;
__device__ __forceinline__ ull_t f2_pack(float lo, float hi) {
    ull_t r;
    asm("mov.b64 %0, {%1, %2};" : "=l"(r) : "f"(lo), "f"(hi));
    return r;
}
__device__ __forceinline__ ull_t f2_mul(ull_t a, ull_t b) {
    ull_t r;
    asm("mul.rn.f32x2 %0, %1, %2;" : "=l"(r) : "l"(a), "l"(b));
    return r;
}
__device__ __forceinline__ ull_t f2_add(ull_t a, ull_t b) {
    ull_t r;
    asm("add.rn.f32x2 %0, %1, %2;" : "=l"(r) : "l"(a), "l"(b));
    return r;
}

__global__ void __launch_bounds__(256)
exp_kernel() {
    __shared__ double red[256];
    int z, by, bx; float w;
    tile_decode(blockIdx.x, z, by, bx, w);

    double m = g_distsum[z] * (1.0 / ((double)BSZ * (double)BSZ));
    float c = (float)(-1.4426950408889634 / (4.0 * m));

    const uint4* src = (const uint4*)(g_dist + (size_t)blockIdx.x * TILE_ELEMS);

    uint4 v[8];
    #pragma unroll
    for (int it = 0; it < 8; it++) v[it] = src[it * 256 + threadIdx.x];

    ull_t s2 = 0ull;                        // packed (0.f, 0.f)
    #pragma unroll
    for (int it = 0; it < 8; it++) {
        uint32_t ww[4] = {v[it].x, v[it].y, v[it].z, v[it].w};
        #pragma unroll
        for (int u = 0; u < 4; u++) {
            float2 f = __half22float2(*(__half2*)&ww[u]);
            float e0, e1;
            asm("ex2.approx.ftz.f32 %0, %1;" : "=f"(e0) : "f"(f.x * c));
            asm("ex2.approx.ftz.f32 %0, %1;" : "=f"(e1) : "f"(f.y * c));
            ull_t e  = f2_pack(e0, e1);
            ull_t q2 = f2_mul(e, e);
            ull_t q4 = f2_mul(q2, q2);
            ull_t q8 = f2_mul(q4, q4);
            ull_t q16 = f2_mul(q8, q8);
            s2 = f2_add(s2, f2_add(f2_add(e, q2), f2_add(q4, q8)));
            s2 = f2_add(s2, q16);
        }
    }
    float sl, sh;
    asm("mov.b64 {%0, %1}, %2;" : "=f"(sl), "=f"(sh) : "l"(s2));
    float lsum = sl + sh;

    red[threadIdx.x] = (double)lsum;
    __syncthreads();
    #pragma unroll
    for (int s = 128; s > 0; s >>= 1) {
        if (threadIdx.x < s) red[threadIdx.x] += red[threadIdx.x + s];
        __syncthreads();
    }
    if (threadIdx.x == 0) atomicAdd(&g_expsum[z], red[0] * (double)w);
}

// ---------------------------------------------------------------------------
__global__ void final_kernel(float* out) {
    double total = g_expsum[0] + g_expsum[1] - 2.0 * g_expsum[2];
    double v = total / ((double)BSZ * ((double)BSZ - 1.0));
    float loss = sqrtf((float)v);
    out[0] = isnan(loss) ? 0.f : loss;
}

// ---------------------------------------------------------------------------
extern "C" void kernel_launch(void* const* d_in, const int* in_sizes, int n_in,
                              void* d_out, int out_size) {
    const float* xs = (const float*)d_in[0];
    const float* xt = (const float*)d_in[1];
    float* out = (float*)d_out;

    static int configured = 0;
    if (!configured) {
        cudaFuncSetAttribute(dist_tc_kernel,
                             cudaFuncAttributeMaxDynamicSharedMemorySize, SM_BYTES);
        configured = 1;
    }

    prep_kernel<<<1024, 256>>>(xs, xt);
    dist_tc_kernel<<<TILES_ALL, 256, SM_BYTES>>>();
    exp_kernel<<<TILES_ALL, 256>>>();
    final_kernel<<<1, 1>>>(out);
}